// round 15
// baseline (speedup 1.0000x reference)
#include <cuda_runtime.h>
#include <mma.h>
#include <cstdint>

using namespace nvcuda;
typedef __half half_t;

// Problem dims: B=8, S=512, D=2048, H=32, HD=64, I=8192, NT=4096 tokens.

// ---------------- scratch (device globals; no allocation allowed) --------
__device__ float  g_tmp[4096 * 8192];    // gate|up fused fp16 [4096][16384]
__device__ float  g_up [4096 * 8192];    // ffn_out fp16 (aliased)
__device__ float  g_rm [1023];           // rel_pos row means
// fp16 operands
__device__ half_t g_xh   [4096 * 2048];
__device__ half_t g_qkvh [4096 * 6144];
__device__ half_t g_ctxh [4096 * 2048];
__device__ half_t g_h1h  [4096 * 2048];
__device__ half_t g_acth [4096 * 8192];  // attn_out fp16
__device__ half_t g_wqkvh[2048 * 6144];  // [K=2048][Nq|Nk|Nv]
__device__ half_t g_woh  [2048 * 2048];
__device__ half_t g_guwh [2048 * 16384]; // [K=2048][gate8192|up8192]
__device__ half_t g_dwh  [8192 * 2048];

// ---------------- small helpers ------------------------------------------
__device__ __forceinline__ uint32_t smem_u32(const void* p) {
    uint32_t a;
    asm("{ .reg .u64 t; cvta.to.shared.u64 t, %1; cvt.u32.u64 %0, t; }"
        : "=r"(a) : "l"(p));
    return a;
}
__device__ __forceinline__ void cpa16(uint32_t dst, const void* src) {
    asm volatile("cp.async.cg.shared.global [%0], [%1], 16;"
                 :: "r"(dst), "l"(src) : "memory");
}
__device__ __forceinline__ void cpa_commit() {
    asm volatile("cp.async.commit_group;" ::: "memory");
}
template <int N>
__device__ __forceinline__ void cpa_wait() {
    asm volatile("cp.async.wait_group %0;" :: "n"(N) : "memory");
}
__device__ __forceinline__ float silu1(float g) {
    return g / (1.0f + __expf(-g));
}

__device__ __forceinline__ float bred(float v, int op_max) {
    __shared__ float red[8];
    #pragma unroll
    for (int o = 16; o; o >>= 1) {
        float w = __shfl_xor_sync(0xffffffffu, v, o);
        v = op_max ? fmaxf(v, w) : v + w;
    }
    __syncthreads();
    if ((threadIdx.x & 31) == 0) red[threadIdx.x >> 5] = v;
    __syncthreads();
    v = red[threadIdx.x & 7];
    #pragma unroll
    for (int o = 4; o; o >>= 1) {
        float w = __shfl_xor_sync(0xffffffffu, v, o);
        v = op_max ? fmaxf(v, w) : v + w;
    }
    return v;
}

// =================== fp16 GEMM: C[M,N] = A[M,K] @ B[K,N] ==================
// Block tile 128x256, BK=32, 256 threads = 8 warps (2x4), warptile 64x64.
// 4-stage cp.async, ONE __syncthreads per K-iteration.
// SILU_A: A is silu(gate)*up computed on the fly from gu [4096][16384]
// (gate at col k, up at col 8192+k); logical K=8192.
#define G2_LDA   40
#define G2_LDB   264
#define G2_ASTG  10240                    // 128*40*2
#define G2_BSTG  16896                    // 32*264*2
#define G2_STG   27136
#define G2_SMEM  (4 * G2_STG)             // 108544
#define G2_LDC   132

template <typename OutT, bool SILU_A>
__global__ void __launch_bounds__(256, 1) gemm2(
    const half_t* __restrict__ A, const half_t* __restrict__ B,
    OutT* __restrict__ C, int M, int N, int K)
{
    extern __shared__ __align__(128) char smem[];
    const uint32_t sb = smem_u32(smem);
    const int tid = threadIdx.x;
    const int warp = tid >> 5;
    const int bm = blockIdx.y * 128, bn = blockIdx.x * 256;
    const int wm = (warp >> 2) * 64, wn = (warp & 3) * 64;

    const int ar0 = tid >> 2,         ac0 = (tid & 3) << 3;
    const int ar1 = (tid + 256) >> 2, ac1 = ((tid + 256) & 3) << 3;
    const int brb = tid >> 5,         bc  = (tid & 31) << 3;

    const half_t* Abm = A + (size_t)bm * (SILU_A ? 16384 : K);
    const half_t* Bbn = B + bn;

    auto load_silu8 = [&](const half_t* gp, uint32_t dst) {
        uint4 gv = *(const uint4*)gp;
        uint4 uv = *(const uint4*)(gp + 8192);
        const half2* g2 = (const half2*)&gv;
        const half2* u2 = (const half2*)&uv;
        uint4 r;
        half2* r2 = (half2*)&r;
        #pragma unroll
        for (int j = 0; j < 4; j++) {
            float2 gf = __half22float2(g2[j]);
            float2 uf = __half22float2(u2[j]);
            r2[j] = __floats2half2_rn(silu1(gf.x) * uf.x, silu1(gf.y) * uf.y);
        }
        asm volatile("st.shared.v4.b32 [%0], {%1,%2,%3,%4};"
                     :: "r"(dst), "r"(r.x), "r"(r.y), "r"(r.z), "r"(r.w)
                     : "memory");
    };

    auto load_stage = [&](int s, int kt) {
        const int k0 = kt * 32;
        uint32_t aB = sb + s * G2_STG;
        uint32_t bB = aB + G2_ASTG;
        if constexpr (SILU_A) {
            load_silu8(Abm + (size_t)ar0 * 16384 + k0 + ac0,
                       aB + (ar0 * G2_LDA + ac0) * 2);
            load_silu8(Abm + (size_t)ar1 * 16384 + k0 + ac1,
                       aB + (ar1 * G2_LDA + ac1) * 2);
        } else {
            cpa16(aB + (ar0 * G2_LDA + ac0) * 2, Abm + (size_t)ar0 * K + k0 + ac0);
            cpa16(aB + (ar1 * G2_LDA + ac1) * 2, Abm + (size_t)ar1 * K + k0 + ac1);
        }
        #pragma unroll
        for (int i = 0; i < 4; i++) {
            int r = brb + 8 * i;
            cpa16(bB + (r * G2_LDB + bc) * 2, Bbn + (size_t)(k0 + r) * N + bc);
        }
    };

    wmma::fragment<wmma::accumulator, 16, 16, 16, float> acc[4][4];
    #pragma unroll
    for (int i = 0; i < 4; i++)
        #pragma unroll
        for (int j = 0; j < 4; j++)
            wmma::fill_fragment(acc[i][j], 0.0f);

    const int KT = K >> 5;
    #pragma unroll
    for (int s = 0; s < 3; s++) { load_stage(s, s); cpa_commit(); }

    for (int kt = 0; kt < KT; kt++) {
        cpa_wait<2>();
        __syncthreads();

        if (kt + 3 < KT) load_stage((kt + 3) & 3, kt + 3);
        cpa_commit();

        const int s = kt & 3;
        const half_t* As = (const half_t*)(smem + s * G2_STG);
        const half_t* Bs = (const half_t*)(smem + s * G2_STG + G2_ASTG);
        #pragma unroll
        for (int ks = 0; ks < 2; ks++) {
            wmma::fragment<wmma::matrix_a, 16, 16, 16, half_t, wmma::row_major> af[4];
            wmma::fragment<wmma::matrix_b, 16, 16, 16, half_t, wmma::row_major> bf[4];
            #pragma unroll
            for (int i = 0; i < 4; i++)
                wmma::load_matrix_sync(af[i], As + (wm + i * 16) * G2_LDA + ks * 16, G2_LDA);
            #pragma unroll
            for (int j = 0; j < 4; j++)
                wmma::load_matrix_sync(bf[j], Bs + (ks * 16) * G2_LDB + wn + j * 16, G2_LDB);
            #pragma unroll
            for (int i = 0; i < 4; i++)
                #pragma unroll
                for (int j = 0; j < 4; j++)
                    wmma::mma_sync(acc[i][j], af[i], bf[j], acc[i][j]);
        }
    }

    // 2-phase epilogue through fp32 smem staging
    float* Cs = (float*)smem;
    #pragma unroll
    for (int ph = 0; ph < 2; ph++) {
        __syncthreads();
        if (((warp & 3) >> 1) == ph) {
            int lwn = (warp & 3) & 1;
            #pragma unroll
            for (int i = 0; i < 4; i++)
                #pragma unroll
                for (int j = 0; j < 4; j++)
                    wmma::store_matrix_sync(Cs + (wm + i * 16) * G2_LDC + lwn * 64 + j * 16,
                                            acc[i][j], G2_LDC, wmma::mem_row_major);
        }
        __syncthreads();
        #pragma unroll
        for (int it = 0; it < 16; it++) {
            int idx = tid + 256 * it;
            int r = idx >> 5, c = (idx & 31) << 2;
            float4 v = *(float4*)(Cs + r * G2_LDC + c);
            if constexpr (sizeof(OutT) == 4) {
                *(float4*)((float*)C + (size_t)(bm + r) * N + bn + ph * 128 + c) = v;
            } else {
                half2 h0 = __floats2half2_rn(v.x, v.y);
                half2 h1 = __floats2half2_rn(v.z, v.w);
                *(uint2*)((half_t*)C + (size_t)(bm + r) * N + bn + ph * 128 + c) =
                    make_uint2(*(uint32_t*)&h0, *(uint32_t*)&h1);
            }
        }
    }
}

// =================== fused flash attention (in-fragment softmax) ==========
#define FL_RM   0
#define FL_QS   4096
#define FL_KS   (FL_QS + 18432)
#define FL_VS   (FL_KS + 18432)
#define FL_PS   (FL_VS + 18432)           // fp16 [128][136] = 34816
#define FL_PMAX (FL_PS + 34816)           // [4][128] f32
#define FL_PSUM (FL_PMAX + 2048)          // [4][128] f32
#define FL_M    (FL_PSUM + 2048)
#define FL_L    (FL_M + 512)
#define FL_CORR (FL_L + 512)
#define FL_SMEM (FL_CORR + 512)           // 99840

__global__ void __launch_bounds__(256, 1) flash_k(
    const half_t* __restrict__ qkv, const float* __restrict__ rmg,
    half_t* __restrict__ ctx)
{
    extern __shared__ __align__(128) char smem[];
    float*  rms  = (float*)(smem + FL_RM);
    half_t* Qs   = (half_t*)(smem + FL_QS);
    half_t* Ks   = (half_t*)(smem + FL_KS);
    half_t* Vs   = (half_t*)(smem + FL_VS);
    half_t* Ps   = (half_t*)(smem + FL_PS);
    float*  pmax = (float*)(smem + FL_PMAX);
    float*  psum = (float*)(smem + FL_PSUM);
    float*  mS   = (float*)(smem + FL_M);
    float*  lS   = (float*)(smem + FL_L);
    float*  cS   = (float*)(smem + FL_CORR);

    const int tid = threadIdx.x, warp = tid >> 5, lane = tid & 31;
    const int bz = blockIdx.y, b = bz >> 5, h = bz & 31;
    const int q0 = blockIdx.x * 128;
    const int wm = (warp >> 2) * 64, wnc = (warp & 3) * 32;
    const int lr = lane >> 2, lc = (lane & 3) * 2;

    for (int i = tid; i < 1023; i += 256) rms[i] = rmg[i];

    const half_t* qp = qkv + ((size_t)(b * 512 + q0)) * 6144 + h * 64;
    #pragma unroll
    for (int i = 0; i < 4; i++) {
        int idx = tid + 256 * i;
        int r = idx >> 3, c = (idx & 7) << 3;
        *(uint4*)(Qs + r * 72 + c) = *(const uint4*)(qp + (size_t)r * 6144 + c);
    }
    if (tid < 128) { mS[tid] = -1e30f; lS[tid] = 0.0f; }

    wmma::fragment<wmma::accumulator, 16, 16, 16, float> oa[4];
    #pragma unroll
    for (int j = 0; j < 4; j++) wmma::fill_fragment(oa[j], 0.0f);

    __syncthreads();

    for (int kt = 0; kt < 4; kt++) {
        const int k0 = kt * 128;
        const half_t* kp = qkv + ((size_t)(b * 512 + k0)) * 6144 + 2048 + h * 64;
        const half_t* vp = qkv + ((size_t)(b * 512 + k0)) * 6144 + 4096 + h * 64;
        #pragma unroll
        for (int i = 0; i < 4; i++) {
            int idx = tid + 256 * i;
            int r = idx >> 3, c = (idx & 7) << 3;
            *(uint4*)(Ks + r * 72 + c) = *(const uint4*)(kp + (size_t)r * 6144 + c);
            *(uint4*)(Vs + r * 72 + c) = *(const uint4*)(vp + (size_t)r * 6144 + c);
        }
        __syncthreads();

        // ---- S = Q @ K^T, kept in fragments ----
        wmma::fragment<wmma::accumulator, 16, 16, 16, float> sa[4][2];
        #pragma unroll
        for (int i = 0; i < 4; i++)
            #pragma unroll
            for (int j = 0; j < 2; j++)
                wmma::fill_fragment(sa[i][j], 0.0f);
        #pragma unroll
        for (int ks = 0; ks < 4; ks++) {
            wmma::fragment<wmma::matrix_a, 16, 16, 16, half_t, wmma::row_major> af[4];
            wmma::fragment<wmma::matrix_b, 16, 16, 16, half_t, wmma::col_major> bf[2];
            #pragma unroll
            for (int i = 0; i < 4; i++)
                wmma::load_matrix_sync(af[i], Qs + (wm + i * 16) * 72 + ks * 16, 72);
            #pragma unroll
            for (int j = 0; j < 2; j++)
                wmma::load_matrix_sync(bf[j], Ks + (wnc + j * 16) * 72 + ks * 16, 72);
            #pragma unroll
            for (int i = 0; i < 4; i++)
                #pragma unroll
                for (int j = 0; j < 2; j++)
                    wmma::mma_sync(sa[i][j], af[i], bf[j], sa[i][j]);
        }

        // ---- in-place scale+bias, per-thread row maxes ----
        float pmx[8];
        #pragma unroll
        for (int k = 0; k < 8; k++) pmx[k] = -1e30f;
        #pragma unroll
        for (int i = 0; i < 4; i++)
            #pragma unroll
            for (int j = 0; j < 2; j++)
                #pragma unroll
                for (int p = 0; p < 4; p++) {
                    int r = wm + i * 16 + lr + ((p & 1) << 3);
                    int c = wnc + j * 16 + lc + ((p >> 1) << 3);
                    int o = k0 + c - q0 - r + 511;
                    float v0 = sa[i][j].x[2 * p] * 0.125f + rms[o];
                    float v1 = sa[i][j].x[2 * p + 1] * 0.125f + rms[o + 1];
                    sa[i][j].x[2 * p] = v0;
                    sa[i][j].x[2 * p + 1] = v1;
                    int rid = i * 2 + (p & 1);
                    pmx[rid] = fmaxf(pmx[rid], fmaxf(v0, v1));
                }
        #pragma unroll
        for (int k = 0; k < 8; k++) {
            pmx[k] = fmaxf(pmx[k], __shfl_xor_sync(0xffffffffu, pmx[k], 1));
            pmx[k] = fmaxf(pmx[k], __shfl_xor_sync(0xffffffffu, pmx[k], 2));
        }
        if ((lane & 3) == 0) {
            #pragma unroll
            for (int i = 0; i < 4; i++) {
                pmax[(warp & 3) * 128 + wm + i * 16 + lr]     = pmx[i * 2];
                pmax[(warp & 3) * 128 + wm + i * 16 + lr + 8] = pmx[i * 2 + 1];
            }
        }
        __syncthreads();

        // ---- row stats (designated lanes) ----
        if ((warp & 3) == 0 && (lane & 3) == 0) {
            #pragma unroll
            for (int i = 0; i < 4; i++)
                #pragma unroll
                for (int h2 = 0; h2 < 2; h2++) {
                    int r = wm + i * 16 + lr + h2 * 8;
                    float mo = mS[r];
                    float mn = fmaxf(fmaxf(fmaxf(pmax[r], pmax[128 + r]),
                                           fmaxf(pmax[256 + r], pmax[384 + r])), mo);
                    cS[r] = __expf(mo - mn);
                    mS[r] = mn;
                }
        }
        __syncthreads();

        // ---- exp in-fragment -> Ps, partial row sums ----
        float mn8[8];
        #pragma unroll
        for (int i = 0; i < 4; i++) {
            mn8[i * 2]     = mS[wm + i * 16 + lr];
            mn8[i * 2 + 1] = mS[wm + i * 16 + lr + 8];
        }
        float psm[8];
        #pragma unroll
        for (int k = 0; k < 8; k++) psm[k] = 0.0f;
        #pragma unroll
        for (int i = 0; i < 4; i++)
            #pragma unroll
            for (int j = 0; j < 2; j++)
                #pragma unroll
                for (int p = 0; p < 4; p++) {
                    int rid = i * 2 + (p & 1);
                    int r = wm + i * 16 + lr + ((p & 1) << 3);
                    int c = wnc + j * 16 + lc + ((p >> 1) << 3);
                    float e0 = __expf(sa[i][j].x[2 * p]     - mn8[rid]);
                    float e1 = __expf(sa[i][j].x[2 * p + 1] - mn8[rid]);
                    psm[rid] += e0 + e1;
                    *(half2*)(Ps + r * 136 + c) = __floats2half2_rn(e0, e1);
                }
        #pragma unroll
        for (int k = 0; k < 8; k++) {
            psm[k] += __shfl_xor_sync(0xffffffffu, psm[k], 1);
            psm[k] += __shfl_xor_sync(0xffffffffu, psm[k], 2);
        }
        if ((lane & 3) == 0) {
            #pragma unroll
            for (int i = 0; i < 4; i++) {
                psum[(warp & 3) * 128 + wm + i * 16 + lr]     = psm[i * 2];
                psum[(warp & 3) * 128 + wm + i * 16 + lr + 8] = psm[i * 2 + 1];
            }
        }
        __syncthreads();

        // ---- lS update (designated) overlaps O rescale + PV (all) ----
        if ((warp & 3) == 0 && (lane & 3) == 0) {
            #pragma unroll
            for (int i = 0; i < 4; i++)
                #pragma unroll
                for (int h2 = 0; h2 < 2; h2++) {
                    int r = wm + i * 16 + lr + h2 * 8;
                    lS[r] = lS[r] * cS[r] +
                            (psum[r] + psum[128 + r]) + (psum[256 + r] + psum[384 + r]);
                }
        }
        {
            float co0 = cS[warp * 16 + lr];
            float co1 = cS[warp * 16 + lr + 8];
            #pragma unroll
            for (int j = 0; j < 4; j++) {
                oa[j].x[0] *= co0; oa[j].x[1] *= co0;
                oa[j].x[4] *= co0; oa[j].x[5] *= co0;
                oa[j].x[2] *= co1; oa[j].x[3] *= co1;
                oa[j].x[6] *= co1; oa[j].x[7] *= co1;
            }
            #pragma unroll
            for (int ks = 0; ks < 8; ks++) {
                wmma::fragment<wmma::matrix_a, 16, 16, 16, half_t, wmma::row_major> af;
                wmma::fragment<wmma::matrix_b, 16, 16, 16, half_t, wmma::row_major> bf[4];
                wmma::load_matrix_sync(af, Ps + (warp * 16) * 136 + ks * 16, 136);
                #pragma unroll
                for (int j = 0; j < 4; j++)
                    wmma::load_matrix_sync(bf[j], Vs + (ks * 16) * 72 + j * 16, 72);
                #pragma unroll
                for (int j = 0; j < 4; j++)
                    wmma::mma_sync(oa[j], af, bf[j], oa[j]);
            }
        }
        __syncthreads();
    }

    // ---- final: O /= l, stage into dead Ks/Vs region, write fp16 ----
    float* Os = (float*)(smem + FL_KS);
    {
        float inv0 = 1.0f / lS[warp * 16 + lr];
        float inv1 = 1.0f / lS[warp * 16 + lr + 8];
        #pragma unroll
        for (int j = 0; j < 4; j++) {
            oa[j].x[0] *= inv0; oa[j].x[1] *= inv0;
            oa[j].x[4] *= inv0; oa[j].x[5] *= inv0;
            oa[j].x[2] *= inv1; oa[j].x[3] *= inv1;
            oa[j].x[6] *= inv1; oa[j].x[7] *= inv1;
        }
        #pragma unroll
        for (int j = 0; j < 4; j++)
            wmma::store_matrix_sync(Os + (warp * 16) * 72 + j * 16,
                                    oa[j], 72, wmma::mem_row_major);
    }
    __syncthreads();

    half_t* cp = ctx + ((size_t)(b * 512 + q0)) * 2048 + h * 64;
    #pragma unroll
    for (int i = 0; i < 8; i++) {
        int idx = tid + 256 * i;
        int r = idx >> 4, c = (idx & 15) << 2;
        float4 ov = *(float4*)(Os + r * 72 + c);
        half2 h0 = __floats2half2_rn(ov.x, ov.y);
        half2 h1 = __floats2half2_rn(ov.z, ov.w);
        *(uint2*)(cp + (size_t)r * 2048 + c) =
            make_uint2(*(uint32_t*)&h0, *(uint32_t*)&h1);
    }
}

// ---------------- residual add + layernorm (row = 2048) ------------------
// XT/YT = float or half. Writes fp32 out (if non-null) and fp16 hout (if non-null).
template <typename XT, typename YT>
__global__ void __launch_bounds__(256) add_ln_k(
    const XT* __restrict__ xr, const YT* __restrict__ yr,
    const float* __restrict__ g, const float* __restrict__ bt,
    float* __restrict__ out, half_t* __restrict__ hout)
{
    size_t row = blockIdx.x;
    int t = threadIdx.x;
    float v[8];
    #pragma unroll
    for (int i = 0; i < 2; i++) {
        int c4 = t + 256 * i;
        float xv[4], yv[4];
        if constexpr (sizeof(XT) == 4) {
            float4 a = *(const float4*)((const float*)xr + row * 2048 + c4 * 4);
            xv[0] = a.x; xv[1] = a.y; xv[2] = a.z; xv[3] = a.w;
        } else {
            uint2 p = *(const uint2*)((const half_t*)xr + row * 2048 + c4 * 4);
            float2 f0 = __half22float2(*(half2*)&p.x);
            float2 f1 = __half22float2(*(half2*)&p.y);
            xv[0] = f0.x; xv[1] = f0.y; xv[2] = f1.x; xv[3] = f1.y;
        }
        if constexpr (sizeof(YT) == 4) {
            float4 c = *(const float4*)((const float*)yr + row * 2048 + c4 * 4);
            yv[0] = c.x; yv[1] = c.y; yv[2] = c.z; yv[3] = c.w;
        } else {
            uint2 p = *(const uint2*)((const half_t*)yr + row * 2048 + c4 * 4);
            float2 f0 = __half22float2(*(half2*)&p.x);
            float2 f1 = __half22float2(*(half2*)&p.y);
            yv[0] = f0.x; yv[1] = f0.y; yv[2] = f1.x; yv[3] = f1.y;
        }
        v[4 * i + 0] = xv[0] + yv[0]; v[4 * i + 1] = xv[1] + yv[1];
        v[4 * i + 2] = xv[2] + yv[2]; v[4 * i + 3] = xv[3] + yv[3];
    }
    float s = 0.0f;
    #pragma unroll
    for (int i = 0; i < 8; i++) s += v[i];
    float mu = bred(s, 0) * (1.0f / 2048.0f);
    float qs = 0.0f;
    #pragma unroll
    for (int i = 0; i < 8; i++) { float d = v[i] - mu; qs += d * d; }
    float rstd = rsqrtf(bred(qs, 0) * (1.0f / 2048.0f) + 1e-6f);
    #pragma unroll
    for (int i = 0; i < 2; i++) {
        int c4 = t + 256 * i;
        float4 gv = ((const float4*)g)[c4];
        float4 bv = ((const float4*)bt)[c4];
        float4 o;
        o.x = (v[4 * i + 0] - mu) * rstd * gv.x + bv.x;
        o.y = (v[4 * i + 1] - mu) * rstd * gv.y + bv.y;
        o.z = (v[4 * i + 2] - mu) * rstd * gv.z + bv.z;
        o.w = (v[4 * i + 3] - mu) * rstd * gv.w + bv.w;
        if (out) *(float4*)(out + row * 2048 + c4 * 4) = o;
        if (hout) {
            half2 h0 = __floats2half2_rn(o.x, o.y);
            half2 h1 = __floats2half2_rn(o.z, o.w);
            *(uint2*)(hout + row * 2048 + c4 * 4) =
                make_uint2(*(uint32_t*)&h0, *(uint32_t*)&h1);
        }
    }
}

// ---------------- conversions ---------------------------------------------
__device__ __forceinline__ void conv16(const float* in, half_t* out) {
    float4 a0 = *(const float4*)(in + 0);
    float4 a1 = *(const float4*)(in + 4);
    float4 a2 = *(const float4*)(in + 8);
    float4 a3 = *(const float4*)(in + 12);
    half2 h0 = __floats2half2_rn(a0.x, a0.y), h1 = __floats2half2_rn(a0.z, a0.w);
    half2 h2 = __floats2half2_rn(a1.x, a1.y), h3 = __floats2half2_rn(a1.z, a1.w);
    half2 h4 = __floats2half2_rn(a2.x, a2.y), h5 = __floats2half2_rn(a2.z, a2.w);
    half2 h6 = __floats2half2_rn(a3.x, a3.y), h7 = __floats2half2_rn(a3.z, a3.w);
    *(uint4*)(out + 0) = make_uint4(*(uint32_t*)&h0, *(uint32_t*)&h1,
                                    *(uint32_t*)&h2, *(uint32_t*)&h3);
    *(uint4*)(out + 8) = make_uint4(*(uint32_t*)&h4, *(uint32_t*)&h5,
                                    *(uint32_t*)&h6, *(uint32_t*)&h7);
}

// stream 0: x + wq/wk/wv + rowmean (everything QKV GEMM needs)
__global__ void __launch_bounds__(256) conv_qkv(
    const float* __restrict__ x,  half_t* __restrict__ xo,
    const float* __restrict__ wq, const float* __restrict__ wk,
    const float* __restrict__ wv, half_t* __restrict__ wqkv,
    const float* __restrict__ rel, float* __restrict__ rm)
{
    int blk = blockIdx.x;
    const int t = threadIdx.x;
    if (blk >= 5120) {
        int r = (blk - 5120) * 256 + t;
        if (r < 1023) {
            float s = 0.0f;
            #pragma unroll
            for (int d = 0; d < 64; d += 4) {
                float4 vv = *(const float4*)(rel + (size_t)r * 64 + d);
                s += (vv.x + vv.y) + (vv.z + vv.w);
            }
            rm[r] = s * (1.0f / 64.0f);
        }
        return;
    }
    if (blk < 2048) {
        size_t i = ((size_t)blk * 256 + t) * 16;
        conv16(x + i, xo + i);
        return;
    }
    int sec = (blk - 2048) >> 10;
    const float* in = sec == 0 ? wq : (sec == 1 ? wk : wv);
    size_t i = ((size_t)((blk - 2048) & 1023) * 256 + t) * 16;
    int r = (int)(i >> 11), c = (int)(i & 2047);
    conv16(in + i, wqkv + (size_t)r * 6144 + sec * 2048 + c);
}

// stream 2 (overlapped): wo + gw|uw fused contiguous + dw
__global__ void __launch_bounds__(256) conv_rest(
    const float* __restrict__ wo, half_t* __restrict__ woo,
    const float* __restrict__ gw, const float* __restrict__ uw,
    half_t* __restrict__ guw,
    const float* __restrict__ dw, half_t* __restrict__ dwo)
{
    int blk = blockIdx.x;
    const int t = threadIdx.x;
    if (blk < 1024) {
        size_t i = ((size_t)blk * 256 + t) * 16;
        conv16(wo + i, woo + i);
        return;
    }
    if (blk < 5120) {
        size_t i = ((size_t)(blk - 1024) * 256 + t) * 16;
        size_t r = i >> 13, c = i & 8191;
        conv16(gw + i, guw + r * 16384 + c);
        return;
    }
    if (blk < 9216) {
        size_t i = ((size_t)(blk - 5120) * 256 + t) * 16;
        size_t r = i >> 13, c = i & 8191;
        conv16(uw + i, guw + r * 16384 + 8192 + c);
        return;
    }
    size_t i = ((size_t)(blk - 9216) * 256 + t) * 16;
    conv16(dw + i, dwo + i);
}

// =================== host side ============================================
extern "C" void kernel_launch(void* const* d_in, const int* in_sizes, int n_in,
                              void* d_out, int out_size)
{
    (void)in_sizes; (void)n_in; (void)out_size;
    const float* x    = (const float*)d_in[0];
    const float* wq   = (const float*)d_in[1];
    const float* wk   = (const float*)d_in[2];
    const float* wv   = (const float*)d_in[3];
    const float* wo   = (const float*)d_in[4];
    const float* rel  = (const float*)d_in[5];
    const float* ln1g = (const float*)d_in[6];
    const float* ln1b = (const float*)d_in[7];
    const float* gw   = (const float*)d_in[8];
    const float* uw   = (const float*)d_in[9];
    const float* dw   = (const float*)d_in[10];
    const float* ln2g = (const float*)d_in[11];
    const float* ln2b = (const float*)d_in[12];
    float* out = (float*)d_out;

    float *tmp, *up, *rm;
    half_t *xh, *qkvh, *ctxh, *h1h, *acth;
    half_t *wqkvh, *woh, *guwh, *dwh;
    cudaGetSymbolAddress((void**)&tmp,   g_tmp);
    cudaGetSymbolAddress((void**)&up,    g_up);
    cudaGetSymbolAddress((void**)&rm,    g_rm);
    cudaGetSymbolAddress((void**)&xh,    g_xh);
    cudaGetSymbolAddress((void**)&qkvh,  g_qkvh);
    cudaGetSymbolAddress((void**)&ctxh,  g_ctxh);
    cudaGetSymbolAddress((void**)&h1h,   g_h1h);
    cudaGetSymbolAddress((void**)&acth,  g_acth);
    cudaGetSymbolAddress((void**)&wqkvh, g_wqkvh);
    cudaGetSymbolAddress((void**)&woh,   g_woh);
    cudaGetSymbolAddress((void**)&guwh,  g_guwh);
    cudaGetSymbolAddress((void**)&dwh,   g_dwh);

    half_t* gu_h   = (half_t*)tmp;   // fused gate|up output [4096][16384]
    half_t* attn_h = acth;           // attn_out fp16
    half_t* ffn_h  = (half_t*)up;    // down-proj fp16 output

    static cudaStream_t s2 = nullptr;
    static cudaEvent_t evFork = nullptr, evJoin = nullptr;
    if (!s2) {
        cudaStreamCreateWithFlags(&s2, cudaStreamNonBlocking);
        cudaEventCreateWithFlags(&evFork, cudaEventDisableTiming);
        cudaEventCreateWithFlags(&evJoin, cudaEventDisableTiming);
    }

    cudaFuncSetAttribute((const void*)gemm2<half_t, false>,
        cudaFuncAttributeMaxDynamicSharedMemorySize, G2_SMEM);
    cudaFuncSetAttribute((const void*)gemm2<half_t, true>,
        cudaFuncAttributeMaxDynamicSharedMemorySize, G2_SMEM);
    cudaFuncSetAttribute((const void*)flash_k,
        cudaFuncAttributeMaxDynamicSharedMemorySize, FL_SMEM);

    // fork: FFN/WO weight conversion overlaps QKV GEMM + flash on stream s2
    cudaEventRecord(evFork, 0);
    cudaStreamWaitEvent(s2, evFork, 0);
    conv_rest<<<13312, 256, 0, s2>>>(wo, woh, gw, uw, guwh, dw, dwh);

    // main stream: QKV-critical conversions, then QKV GEMM + flash
    conv_qkv<<<5124, 256>>>(x, xh, wq, wk, wv, wqkvh, rel, rm);
    gemm2<half_t, false><<<dim3(24, 32), 256, G2_SMEM>>>(
        xh, wqkvh, qkvh, 4096, 6144, 2048);
    flash_k<<<dim3(4, 256), 256, FL_SMEM>>>(qkvh, rm, ctxh);

    // join: WO GEMM needs woh from s2
    cudaEventRecord(evJoin, s2);
    cudaStreamWaitEvent(0, evJoin, 0);

    // output projection + residual + LN1 (fp16 h1 only)
    gemm2<half_t, false><<<dim3(8, 32), 256, G2_SMEM>>>(
        ctxh, woh, attn_h, 4096, 2048, 2048);
    add_ln_k<float, half_t><<<4096, 256>>>(x, attn_h, ln1g, ln1b, nullptr, h1h);

    // FFN: fused gate|up GEMM (N=16384), then down-proj with in-loader silu
    gemm2<half_t, false><<<dim3(64, 32), 256, G2_SMEM>>>(
        h1h, guwh, gu_h, 4096, 16384, 2048);
    gemm2<half_t, true><<<dim3(8, 32), 256, G2_SMEM>>>(
        gu_h, dwh, ffn_h, 4096, 2048, 8192);

    // residual (fp16 h1) + LN2 -> output
    add_ln_k<half_t, half_t><<<4096, 256>>>(h1h, ffn_h, ln2g, ln2b, out, nullptr);
}

// round 16
// speedup vs baseline: 1.3859x; 1.3859x over previous
#include <cuda_runtime.h>
#include <mma.h>
#include <cstdint>

using namespace nvcuda;
typedef __half half_t;

// Problem dims: B=8, S=512, D=2048, H=32, HD=64, I=8192, NT=4096 tokens.

// ---------------- scratch (device globals; no allocation allowed) --------
__device__ float  g_tmp[4096 * 8192];    // gate|up fused fp16 [4096][16384]
__device__ float  g_up [4096 * 8192];    // ffn_out fp16 (aliased)
__device__ float  g_rm [1023];           // rel_pos row means
// fp16 operands
__device__ half_t g_xh   [4096 * 2048];
__device__ half_t g_qkvh [4096 * 6144];
__device__ half_t g_ctxh [4096 * 2048];
__device__ half_t g_h1h  [4096 * 2048];
__device__ half_t g_acth [4096 * 8192];  // attn_out fp16, later silu act
__device__ half_t g_wqkvh[2048 * 6144];  // [K=2048][Nq|Nk|Nv]
__device__ half_t g_woh  [2048 * 2048];
__device__ half_t g_guwh [2048 * 16384]; // [K=2048][gate8192|up8192]
__device__ half_t g_dwh  [8192 * 2048];

// ---------------- small helpers ------------------------------------------
__device__ __forceinline__ uint32_t smem_u32(const void* p) {
    uint32_t a;
    asm("{ .reg .u64 t; cvta.to.shared.u64 t, %1; cvt.u32.u64 %0, t; }"
        : "=r"(a) : "l"(p));
    return a;
}
__device__ __forceinline__ void cpa16(uint32_t dst, const void* src) {
    asm volatile("cp.async.cg.shared.global [%0], [%1], 16;"
                 :: "r"(dst), "l"(src) : "memory");
}
__device__ __forceinline__ void cpa_commit() {
    asm volatile("cp.async.commit_group;" ::: "memory");
}
template <int N>
__device__ __forceinline__ void cpa_wait() {
    asm volatile("cp.async.wait_group %0;" :: "n"(N) : "memory");
}

__device__ __forceinline__ float bred(float v, int op_max) {
    __shared__ float red[8];
    #pragma unroll
    for (int o = 16; o; o >>= 1) {
        float w = __shfl_xor_sync(0xffffffffu, v, o);
        v = op_max ? fmaxf(v, w) : v + w;
    }
    __syncthreads();
    if ((threadIdx.x & 31) == 0) red[threadIdx.x >> 5] = v;
    __syncthreads();
    v = red[threadIdx.x & 7];
    #pragma unroll
    for (int o = 4; o; o >>= 1) {
        float w = __shfl_xor_sync(0xffffffffu, v, o);
        v = op_max ? fmaxf(v, w) : v + w;
    }
    return v;
}

// =================== fp16 GEMM: C[M,N] = A[M,K] @ B[K,N] ==================
// Block tile 128x256, BK=32, 256 threads = 8 warps (2x4), warptile 64x64.
// 4-stage cp.async, ONE __syncthreads per K-iteration. (Best-measured config.)
#define G2_LDA   40
#define G2_LDB   264
#define G2_ASTG  10240                    // 128*40*2
#define G2_BSTG  16896                    // 32*264*2
#define G2_STG   27136
#define G2_SMEM  (4 * G2_STG)             // 108544
#define G2_LDC   132

template <typename OutT>
__global__ void __launch_bounds__(256, 1) gemm2(
    const half_t* __restrict__ A, const half_t* __restrict__ B,
    OutT* __restrict__ C, int M, int N, int K)
{
    extern __shared__ __align__(128) char smem[];
    const uint32_t sb = smem_u32(smem);
    const int tid = threadIdx.x;
    const int warp = tid >> 5;
    const int bm = blockIdx.y * 128, bn = blockIdx.x * 256;
    const int wm = (warp >> 2) * 64, wn = (warp & 3) * 64;

    const int ar0 = tid >> 2,         ac0 = (tid & 3) << 3;
    const int ar1 = (tid + 256) >> 2, ac1 = ((tid + 256) & 3) << 3;
    const int brb = tid >> 5,         bc  = (tid & 31) << 3;

    const half_t* Abm = A + (size_t)bm * K;
    const half_t* Bbn = B + bn;

    auto load_stage = [&](int s, int kt) {
        const int k0 = kt * 32;
        uint32_t aB = sb + s * G2_STG;
        uint32_t bB = aB + G2_ASTG;
        cpa16(aB + (ar0 * G2_LDA + ac0) * 2, Abm + (size_t)ar0 * K + k0 + ac0);
        cpa16(aB + (ar1 * G2_LDA + ac1) * 2, Abm + (size_t)ar1 * K + k0 + ac1);
        #pragma unroll
        for (int i = 0; i < 4; i++) {
            int r = brb + 8 * i;
            cpa16(bB + (r * G2_LDB + bc) * 2, Bbn + (size_t)(k0 + r) * N + bc);
        }
    };

    wmma::fragment<wmma::accumulator, 16, 16, 16, float> acc[4][4];
    #pragma unroll
    for (int i = 0; i < 4; i++)
        #pragma unroll
        for (int j = 0; j < 4; j++)
            wmma::fill_fragment(acc[i][j], 0.0f);

    const int KT = K >> 5;
    #pragma unroll
    for (int s = 0; s < 3; s++) { load_stage(s, s); cpa_commit(); }

    for (int kt = 0; kt < KT; kt++) {
        cpa_wait<2>();
        __syncthreads();

        if (kt + 3 < KT) load_stage((kt + 3) & 3, kt + 3);
        cpa_commit();

        const int s = kt & 3;
        const half_t* As = (const half_t*)(smem + s * G2_STG);
        const half_t* Bs = (const half_t*)(smem + s * G2_STG + G2_ASTG);
        #pragma unroll
        for (int ks = 0; ks < 2; ks++) {
            wmma::fragment<wmma::matrix_a, 16, 16, 16, half_t, wmma::row_major> af[4];
            wmma::fragment<wmma::matrix_b, 16, 16, 16, half_t, wmma::row_major> bf[4];
            #pragma unroll
            for (int i = 0; i < 4; i++)
                wmma::load_matrix_sync(af[i], As + (wm + i * 16) * G2_LDA + ks * 16, G2_LDA);
            #pragma unroll
            for (int j = 0; j < 4; j++)
                wmma::load_matrix_sync(bf[j], Bs + (ks * 16) * G2_LDB + wn + j * 16, G2_LDB);
            #pragma unroll
            for (int i = 0; i < 4; i++)
                #pragma unroll
                for (int j = 0; j < 4; j++)
                    wmma::mma_sync(acc[i][j], af[i], bf[j], acc[i][j]);
        }
    }

    // 2-phase epilogue through fp32 smem staging
    float* Cs = (float*)smem;
    #pragma unroll
    for (int ph = 0; ph < 2; ph++) {
        __syncthreads();
        if (((warp & 3) >> 1) == ph) {
            int lwn = (warp & 3) & 1;
            #pragma unroll
            for (int i = 0; i < 4; i++)
                #pragma unroll
                for (int j = 0; j < 4; j++)
                    wmma::store_matrix_sync(Cs + (wm + i * 16) * G2_LDC + lwn * 64 + j * 16,
                                            acc[i][j], G2_LDC, wmma::mem_row_major);
        }
        __syncthreads();
        #pragma unroll
        for (int it = 0; it < 16; it++) {
            int idx = tid + 256 * it;
            int r = idx >> 5, c = (idx & 31) << 2;
            float4 v = *(float4*)(Cs + r * G2_LDC + c);
            if constexpr (sizeof(OutT) == 4) {
                *(float4*)((float*)C + (size_t)(bm + r) * N + bn + ph * 128 + c) = v;
            } else {
                half2 h0 = __floats2half2_rn(v.x, v.y);
                half2 h1 = __floats2half2_rn(v.z, v.w);
                *(uint2*)((half_t*)C + (size_t)(bm + r) * N + bn + ph * 128 + c) =
                    make_uint2(*(uint32_t*)&h0, *(uint32_t*)&h1);
            }
        }
    }
}

// =================== fused flash attention (in-fragment softmax) ==========
#define FL_RM   0
#define FL_QS   4096
#define FL_KS   (FL_QS + 18432)
#define FL_VS   (FL_KS + 18432)
#define FL_PS   (FL_VS + 18432)           // fp16 [128][136] = 34816
#define FL_PMAX (FL_PS + 34816)           // [4][128] f32
#define FL_PSUM (FL_PMAX + 2048)          // [4][128] f32
#define FL_M    (FL_PSUM + 2048)
#define FL_L    (FL_M + 512)
#define FL_CORR (FL_L + 512)
#define FL_SMEM (FL_CORR + 512)           // 99840

__global__ void __launch_bounds__(256, 1) flash_k(
    const half_t* __restrict__ qkv, const float* __restrict__ rmg,
    half_t* __restrict__ ctx)
{
    extern __shared__ __align__(128) char smem[];
    float*  rms  = (float*)(smem + FL_RM);
    half_t* Qs   = (half_t*)(smem + FL_QS);
    half_t* Ks   = (half_t*)(smem + FL_KS);
    half_t* Vs   = (half_t*)(smem + FL_VS);
    half_t* Ps   = (half_t*)(smem + FL_PS);
    float*  pmax = (float*)(smem + FL_PMAX);
    float*  psum = (float*)(smem + FL_PSUM);
    float*  mS   = (float*)(smem + FL_M);
    float*  lS   = (float*)(smem + FL_L);
    float*  cS   = (float*)(smem + FL_CORR);

    const int tid = threadIdx.x, warp = tid >> 5, lane = tid & 31;
    const int bz = blockIdx.y, b = bz >> 5, h = bz & 31;
    const int q0 = blockIdx.x * 128;
    const int wm = (warp >> 2) * 64, wnc = (warp & 3) * 32;
    const int lr = lane >> 2, lc = (lane & 3) * 2;

    for (int i = tid; i < 1023; i += 256) rms[i] = rmg[i];

    const half_t* qp = qkv + ((size_t)(b * 512 + q0)) * 6144 + h * 64;
    #pragma unroll
    for (int i = 0; i < 4; i++) {
        int idx = tid + 256 * i;
        int r = idx >> 3, c = (idx & 7) << 3;
        *(uint4*)(Qs + r * 72 + c) = *(const uint4*)(qp + (size_t)r * 6144 + c);
    }
    if (tid < 128) { mS[tid] = -1e30f; lS[tid] = 0.0f; }

    wmma::fragment<wmma::accumulator, 16, 16, 16, float> oa[4];
    #pragma unroll
    for (int j = 0; j < 4; j++) wmma::fill_fragment(oa[j], 0.0f);

    __syncthreads();

    for (int kt = 0; kt < 4; kt++) {
        const int k0 = kt * 128;
        const half_t* kp = qkv + ((size_t)(b * 512 + k0)) * 6144 + 2048 + h * 64;
        const half_t* vp = qkv + ((size_t)(b * 512 + k0)) * 6144 + 4096 + h * 64;
        #pragma unroll
        for (int i = 0; i < 4; i++) {
            int idx = tid + 256 * i;
            int r = idx >> 3, c = (idx & 7) << 3;
            *(uint4*)(Ks + r * 72 + c) = *(const uint4*)(kp + (size_t)r * 6144 + c);
            *(uint4*)(Vs + r * 72 + c) = *(const uint4*)(vp + (size_t)r * 6144 + c);
        }
        __syncthreads();

        // ---- S = Q @ K^T, kept in fragments ----
        wmma::fragment<wmma::accumulator, 16, 16, 16, float> sa[4][2];
        #pragma unroll
        for (int i = 0; i < 4; i++)
            #pragma unroll
            for (int j = 0; j < 2; j++)
                wmma::fill_fragment(sa[i][j], 0.0f);
        #pragma unroll
        for (int ks = 0; ks < 4; ks++) {
            wmma::fragment<wmma::matrix_a, 16, 16, 16, half_t, wmma::row_major> af[4];
            wmma::fragment<wmma::matrix_b, 16, 16, 16, half_t, wmma::col_major> bf[2];
            #pragma unroll
            for (int i = 0; i < 4; i++)
                wmma::load_matrix_sync(af[i], Qs + (wm + i * 16) * 72 + ks * 16, 72);
            #pragma unroll
            for (int j = 0; j < 2; j++)
                wmma::load_matrix_sync(bf[j], Ks + (wnc + j * 16) * 72 + ks * 16, 72);
            #pragma unroll
            for (int i = 0; i < 4; i++)
                #pragma unroll
                for (int j = 0; j < 2; j++)
                    wmma::mma_sync(sa[i][j], af[i], bf[j], sa[i][j]);
        }

        // ---- in-place scale+bias, per-thread row maxes ----
        float pmx[8];
        #pragma unroll
        for (int k = 0; k < 8; k++) pmx[k] = -1e30f;
        #pragma unroll
        for (int i = 0; i < 4; i++)
            #pragma unroll
            for (int j = 0; j < 2; j++)
                #pragma unroll
                for (int p = 0; p < 4; p++) {
                    int r = wm + i * 16 + lr + ((p & 1) << 3);
                    int c = wnc + j * 16 + lc + ((p >> 1) << 3);
                    int o = k0 + c - q0 - r + 511;
                    float v0 = sa[i][j].x[2 * p] * 0.125f + rms[o];
                    float v1 = sa[i][j].x[2 * p + 1] * 0.125f + rms[o + 1];
                    sa[i][j].x[2 * p] = v0;
                    sa[i][j].x[2 * p + 1] = v1;
                    int rid = i * 2 + (p & 1);
                    pmx[rid] = fmaxf(pmx[rid], fmaxf(v0, v1));
                }
        #pragma unroll
        for (int k = 0; k < 8; k++) {
            pmx[k] = fmaxf(pmx[k], __shfl_xor_sync(0xffffffffu, pmx[k], 1));
            pmx[k] = fmaxf(pmx[k], __shfl_xor_sync(0xffffffffu, pmx[k], 2));
        }
        if ((lane & 3) == 0) {
            #pragma unroll
            for (int i = 0; i < 4; i++) {
                pmax[(warp & 3) * 128 + wm + i * 16 + lr]     = pmx[i * 2];
                pmax[(warp & 3) * 128 + wm + i * 16 + lr + 8] = pmx[i * 2 + 1];
            }
        }
        __syncthreads();

        // ---- row stats (designated lanes) ----
        if ((warp & 3) == 0 && (lane & 3) == 0) {
            #pragma unroll
            for (int i = 0; i < 4; i++)
                #pragma unroll
                for (int h2 = 0; h2 < 2; h2++) {
                    int r = wm + i * 16 + lr + h2 * 8;
                    float mo = mS[r];
                    float mn = fmaxf(fmaxf(fmaxf(pmax[r], pmax[128 + r]),
                                           fmaxf(pmax[256 + r], pmax[384 + r])), mo);
                    cS[r] = __expf(mo - mn);
                    mS[r] = mn;
                }
        }
        __syncthreads();

        // ---- exp in-fragment -> Ps, partial row sums ----
        float mn8[8];
        #pragma unroll
        for (int i = 0; i < 4; i++) {
            mn8[i * 2]     = mS[wm + i * 16 + lr];
            mn8[i * 2 + 1] = mS[wm + i * 16 + lr + 8];
        }
        float psm[8];
        #pragma unroll
        for (int k = 0; k < 8; k++) psm[k] = 0.0f;
        #pragma unroll
        for (int i = 0; i < 4; i++)
            #pragma unroll
            for (int j = 0; j < 2; j++)
                #pragma unroll
                for (int p = 0; p < 4; p++) {
                    int rid = i * 2 + (p & 1);
                    int r = wm + i * 16 + lr + ((p & 1) << 3);
                    int c = wnc + j * 16 + lc + ((p >> 1) << 3);
                    float e0 = __expf(sa[i][j].x[2 * p]     - mn8[rid]);
                    float e1 = __expf(sa[i][j].x[2 * p + 1] - mn8[rid]);
                    psm[rid] += e0 + e1;
                    *(half2*)(Ps + r * 136 + c) = __floats2half2_rn(e0, e1);
                }
        #pragma unroll
        for (int k = 0; k < 8; k++) {
            psm[k] += __shfl_xor_sync(0xffffffffu, psm[k], 1);
            psm[k] += __shfl_xor_sync(0xffffffffu, psm[k], 2);
        }
        if ((lane & 3) == 0) {
            #pragma unroll
            for (int i = 0; i < 4; i++) {
                psum[(warp & 3) * 128 + wm + i * 16 + lr]     = psm[i * 2];
                psum[(warp & 3) * 128 + wm + i * 16 + lr + 8] = psm[i * 2 + 1];
            }
        }
        __syncthreads();

        // ---- lS update (designated) overlaps O rescale + PV (all) ----
        if ((warp & 3) == 0 && (lane & 3) == 0) {
            #pragma unroll
            for (int i = 0; i < 4; i++)
                #pragma unroll
                for (int h2 = 0; h2 < 2; h2++) {
                    int r = wm + i * 16 + lr + h2 * 8;
                    lS[r] = lS[r] * cS[r] +
                            (psum[r] + psum[128 + r]) + (psum[256 + r] + psum[384 + r]);
                }
        }
        {
            float co0 = cS[warp * 16 + lr];
            float co1 = cS[warp * 16 + lr + 8];
            #pragma unroll
            for (int j = 0; j < 4; j++) {
                oa[j].x[0] *= co0; oa[j].x[1] *= co0;
                oa[j].x[4] *= co0; oa[j].x[5] *= co0;
                oa[j].x[2] *= co1; oa[j].x[3] *= co1;
                oa[j].x[6] *= co1; oa[j].x[7] *= co1;
            }
            #pragma unroll
            for (int ks = 0; ks < 8; ks++) {
                wmma::fragment<wmma::matrix_a, 16, 16, 16, half_t, wmma::row_major> af;
                wmma::fragment<wmma::matrix_b, 16, 16, 16, half_t, wmma::row_major> bf[4];
                wmma::load_matrix_sync(af, Ps + (warp * 16) * 136 + ks * 16, 136);
                #pragma unroll
                for (int j = 0; j < 4; j++)
                    wmma::load_matrix_sync(bf[j], Vs + (ks * 16) * 72 + j * 16, 72);
                #pragma unroll
                for (int j = 0; j < 4; j++)
                    wmma::mma_sync(oa[j], af, bf[j], oa[j]);
            }
        }
        __syncthreads();
    }

    // ---- final: O /= l, stage into dead Ks/Vs region, write fp16 ----
    float* Os = (float*)(smem + FL_KS);
    {
        float inv0 = 1.0f / lS[warp * 16 + lr];
        float inv1 = 1.0f / lS[warp * 16 + lr + 8];
        #pragma unroll
        for (int j = 0; j < 4; j++) {
            oa[j].x[0] *= inv0; oa[j].x[1] *= inv0;
            oa[j].x[4] *= inv0; oa[j].x[5] *= inv0;
            oa[j].x[2] *= inv1; oa[j].x[3] *= inv1;
            oa[j].x[6] *= inv1; oa[j].x[7] *= inv1;
        }
        #pragma unroll
        for (int j = 0; j < 4; j++)
            wmma::store_matrix_sync(Os + (warp * 16) * 72 + j * 16,
                                    oa[j], 72, wmma::mem_row_major);
    }
    __syncthreads();

    half_t* cp = ctx + ((size_t)(b * 512 + q0)) * 2048 + h * 64;
    #pragma unroll
    for (int i = 0; i < 8; i++) {
        int idx = tid + 256 * i;
        int r = idx >> 4, c = (idx & 15) << 2;
        float4 ov = *(float4*)(Os + r * 72 + c);
        half2 h0 = __floats2half2_rn(ov.x, ov.y);
        half2 h1 = __floats2half2_rn(ov.z, ov.w);
        *(uint2*)(cp + (size_t)r * 2048 + c) =
            make_uint2(*(uint32_t*)&h0, *(uint32_t*)&h1);
    }
}

// ---------------- residual add + layernorm (row = 2048) ------------------
template <typename XT, typename YT>
__global__ void __launch_bounds__(256) add_ln_k(
    const XT* __restrict__ xr, const YT* __restrict__ yr,
    const float* __restrict__ g, const float* __restrict__ bt,
    float* __restrict__ out, half_t* __restrict__ hout)
{
    size_t row = blockIdx.x;
    int t = threadIdx.x;
    float v[8];
    #pragma unroll
    for (int i = 0; i < 2; i++) {
        int c4 = t + 256 * i;
        float xv[4], yv[4];
        if constexpr (sizeof(XT) == 4) {
            float4 a = *(const float4*)((const float*)xr + row * 2048 + c4 * 4);
            xv[0] = a.x; xv[1] = a.y; xv[2] = a.z; xv[3] = a.w;
        } else {
            uint2 p = *(const uint2*)((const half_t*)xr + row * 2048 + c4 * 4);
            float2 f0 = __half22float2(*(half2*)&p.x);
            float2 f1 = __half22float2(*(half2*)&p.y);
            xv[0] = f0.x; xv[1] = f0.y; xv[2] = f1.x; xv[3] = f1.y;
        }
        if constexpr (sizeof(YT) == 4) {
            float4 c = *(const float4*)((const float*)yr + row * 2048 + c4 * 4);
            yv[0] = c.x; yv[1] = c.y; yv[2] = c.z; yv[3] = c.w;
        } else {
            uint2 p = *(const uint2*)((const half_t*)yr + row * 2048 + c4 * 4);
            float2 f0 = __half22float2(*(half2*)&p.x);
            float2 f1 = __half22float2(*(half2*)&p.y);
            yv[0] = f0.x; yv[1] = f0.y; yv[2] = f1.x; yv[3] = f1.y;
        }
        v[4 * i + 0] = xv[0] + yv[0]; v[4 * i + 1] = xv[1] + yv[1];
        v[4 * i + 2] = xv[2] + yv[2]; v[4 * i + 3] = xv[3] + yv[3];
    }
    float s = 0.0f;
    #pragma unroll
    for (int i = 0; i < 8; i++) s += v[i];
    float mu = bred(s, 0) * (1.0f / 2048.0f);
    float qs = 0.0f;
    #pragma unroll
    for (int i = 0; i < 8; i++) { float d = v[i] - mu; qs += d * d; }
    float rstd = rsqrtf(bred(qs, 0) * (1.0f / 2048.0f) + 1e-6f);
    #pragma unroll
    for (int i = 0; i < 2; i++) {
        int c4 = t + 256 * i;
        float4 gv = ((const float4*)g)[c4];
        float4 bv = ((const float4*)bt)[c4];
        float4 o;
        o.x = (v[4 * i + 0] - mu) * rstd * gv.x + bv.x;
        o.y = (v[4 * i + 1] - mu) * rstd * gv.y + bv.y;
        o.z = (v[4 * i + 2] - mu) * rstd * gv.z + bv.z;
        o.w = (v[4 * i + 3] - mu) * rstd * gv.w + bv.w;
        if (out) *(float4*)(out + row * 2048 + c4 * 4) = o;
        if (hout) {
            half2 h0 = __floats2half2_rn(o.x, o.y);
            half2 h1 = __floats2half2_rn(o.z, o.w);
            *(uint2*)(hout + row * 2048 + c4 * 4) =
                make_uint2(*(uint32_t*)&h0, *(uint32_t*)&h1);
        }
    }
}

// ---------------- silu(gate)*up from fused [4096][16384] ------------------
__global__ void __launch_bounds__(256) silu_mul_f(
    const half_t* __restrict__ gu, half_t* __restrict__ act)
{
    size_t idx = ((size_t)blockIdx.x * 256 + threadIdx.x) * 8;
    size_t row = idx >> 13, col = idx & 8191;
    uint4 gp = *(const uint4*)(gu + row * 16384 + col);
    uint4 upk = *(const uint4*)(gu + row * 16384 + 8192 + col);
    const half2* g2 = (const half2*)&gp;
    const half2* u2 = (const half2*)&upk;
    uint4 r;
    half2* r2 = (half2*)&r;
    #pragma unroll
    for (int j = 0; j < 4; j++) {
        float2 gf = __half22float2(g2[j]);
        float2 uf = __half22float2(u2[j]);
        float a = gf.x / (1.0f + __expf(-gf.x)) * uf.x;
        float b = gf.y / (1.0f + __expf(-gf.y)) * uf.y;
        r2[j] = __floats2half2_rn(a, b);
    }
    *(uint4*)(act + idx) = r;
}

// ---------------- conversions ---------------------------------------------
__device__ __forceinline__ void conv16(const float* in, half_t* out) {
    float4 a0 = *(const float4*)(in + 0);
    float4 a1 = *(const float4*)(in + 4);
    float4 a2 = *(const float4*)(in + 8);
    float4 a3 = *(const float4*)(in + 12);
    half2 h0 = __floats2half2_rn(a0.x, a0.y), h1 = __floats2half2_rn(a0.z, a0.w);
    half2 h2 = __floats2half2_rn(a1.x, a1.y), h3 = __floats2half2_rn(a1.z, a1.w);
    half2 h4 = __floats2half2_rn(a2.x, a2.y), h5 = __floats2half2_rn(a2.z, a2.w);
    half2 h6 = __floats2half2_rn(a3.x, a3.y), h7 = __floats2half2_rn(a3.z, a3.w);
    *(uint4*)(out + 0) = make_uint4(*(uint32_t*)&h0, *(uint32_t*)&h1,
                                    *(uint32_t*)&h2, *(uint32_t*)&h3);
    *(uint4*)(out + 8) = make_uint4(*(uint32_t*)&h4, *(uint32_t*)&h5,
                                    *(uint32_t*)&h6, *(uint32_t*)&h7);
}

// stream 0: x + wq/wk/wv + rowmean (everything QKV GEMM needs)
__global__ void __launch_bounds__(256) conv_qkv(
    const float* __restrict__ x,  half_t* __restrict__ xo,
    const float* __restrict__ wq, const float* __restrict__ wk,
    const float* __restrict__ wv, half_t* __restrict__ wqkv,
    const float* __restrict__ rel, float* __restrict__ rm)
{
    int blk = blockIdx.x;
    const int t = threadIdx.x;
    if (blk >= 5120) {
        int r = (blk - 5120) * 256 + t;
        if (r < 1023) {
            float s = 0.0f;
            #pragma unroll
            for (int d = 0; d < 64; d += 4) {
                float4 vv = *(const float4*)(rel + (size_t)r * 64 + d);
                s += (vv.x + vv.y) + (vv.z + vv.w);
            }
            rm[r] = s * (1.0f / 64.0f);
        }
        return;
    }
    if (blk < 2048) {
        size_t i = ((size_t)blk * 256 + t) * 16;
        conv16(x + i, xo + i);
        return;
    }
    int sec = (blk - 2048) >> 10;
    const float* in = sec == 0 ? wq : (sec == 1 ? wk : wv);
    size_t i = ((size_t)((blk - 2048) & 1023) * 256 + t) * 16;
    int r = (int)(i >> 11), c = (int)(i & 2047);
    conv16(in + i, wqkv + (size_t)r * 6144 + sec * 2048 + c);
}

// stream 2 (overlapped): wo + gw|uw fused contiguous + dw
__global__ void __launch_bounds__(256) conv_rest(
    const float* __restrict__ wo, half_t* __restrict__ woo,
    const float* __restrict__ gw, const float* __restrict__ uw,
    half_t* __restrict__ guw,
    const float* __restrict__ dw, half_t* __restrict__ dwo)
{
    int blk = blockIdx.x;
    const int t = threadIdx.x;
    if (blk < 1024) {
        size_t i = ((size_t)blk * 256 + t) * 16;
        conv16(wo + i, woo + i);
        return;
    }
    if (blk < 5120) {
        size_t i = ((size_t)(blk - 1024) * 256 + t) * 16;
        size_t r = i >> 13, c = i & 8191;
        conv16(gw + i, guw + r * 16384 + c);
        return;
    }
    if (blk < 9216) {
        size_t i = ((size_t)(blk - 5120) * 256 + t) * 16;
        size_t r = i >> 13, c = i & 8191;
        conv16(uw + i, guw + r * 16384 + 8192 + c);
        return;
    }
    size_t i = ((size_t)(blk - 9216) * 256 + t) * 16;
    conv16(dw + i, dwo + i);
}

// =================== host side ============================================
extern "C" void kernel_launch(void* const* d_in, const int* in_sizes, int n_in,
                              void* d_out, int out_size)
{
    (void)in_sizes; (void)n_in; (void)out_size;
    const float* x    = (const float*)d_in[0];
    const float* wq   = (const float*)d_in[1];
    const float* wk   = (const float*)d_in[2];
    const float* wv   = (const float*)d_in[3];
    const float* wo   = (const float*)d_in[4];
    const float* rel  = (const float*)d_in[5];
    const float* ln1g = (const float*)d_in[6];
    const float* ln1b = (const float*)d_in[7];
    const float* gw   = (const float*)d_in[8];
    const float* uw   = (const float*)d_in[9];
    const float* dw   = (const float*)d_in[10];
    const float* ln2g = (const float*)d_in[11];
    const float* ln2b = (const float*)d_in[12];
    float* out = (float*)d_out;

    float *tmp, *up, *rm;
    half_t *xh, *qkvh, *ctxh, *h1h, *acth;
    half_t *wqkvh, *woh, *guwh, *dwh;
    cudaGetSymbolAddress((void**)&tmp,   g_tmp);
    cudaGetSymbolAddress((void**)&up,    g_up);
    cudaGetSymbolAddress((void**)&rm,    g_rm);
    cudaGetSymbolAddress((void**)&xh,    g_xh);
    cudaGetSymbolAddress((void**)&qkvh,  g_qkvh);
    cudaGetSymbolAddress((void**)&ctxh,  g_ctxh);
    cudaGetSymbolAddress((void**)&h1h,   g_h1h);
    cudaGetSymbolAddress((void**)&acth,  g_acth);
    cudaGetSymbolAddress((void**)&wqkvh, g_wqkvh);
    cudaGetSymbolAddress((void**)&woh,   g_woh);
    cudaGetSymbolAddress((void**)&guwh,  g_guwh);
    cudaGetSymbolAddress((void**)&dwh,   g_dwh);

    half_t* gu_h   = (half_t*)tmp;   // fused gate|up output [4096][16384]
    half_t* attn_h = acth;           // attn_out (dead before silu writes acth)
    half_t* ffn_h  = (half_t*)up;    // down-proj fp16 output

    static cudaStream_t s2 = nullptr;
    static cudaEvent_t evFork = nullptr, evJoin = nullptr;
    if (!s2) {
        cudaStreamCreateWithFlags(&s2, cudaStreamNonBlocking);
        cudaEventCreateWithFlags(&evFork, cudaEventDisableTiming);
        cudaEventCreateWithFlags(&evJoin, cudaEventDisableTiming);
    }

    cudaFuncSetAttribute((const void*)gemm2<half_t>,
        cudaFuncAttributeMaxDynamicSharedMemorySize, G2_SMEM);
    cudaFuncSetAttribute((const void*)gemm2<float>,
        cudaFuncAttributeMaxDynamicSharedMemorySize, G2_SMEM);
    cudaFuncSetAttribute((const void*)flash_k,
        cudaFuncAttributeMaxDynamicSharedMemorySize, FL_SMEM);

    // fork: FFN/WO weight conversion overlaps QKV GEMM + flash on stream s2
    cudaEventRecord(evFork, 0);
    cudaStreamWaitEvent(s2, evFork, 0);
    conv_rest<<<13312, 256, 0, s2>>>(wo, woh, gw, uw, guwh, dw, dwh);

    // main stream: QKV-critical conversions, then QKV GEMM + flash
    conv_qkv<<<5124, 256>>>(x, xh, wq, wk, wv, wqkvh, rel, rm);
    gemm2<half_t><<<dim3(24, 32), 256, G2_SMEM>>>(xh, wqkvh, qkvh, 4096, 6144, 2048);
    flash_k<<<dim3(4, 256), 256, FL_SMEM>>>(qkvh, rm, ctxh);

    // join: WO GEMM needs woh from s2
    cudaEventRecord(evJoin, s2);
    cudaStreamWaitEvent(0, evJoin, 0);

    // output projection + residual + LN1 (fp16 h1 only)
    gemm2<half_t><<<dim3(8, 32), 256, G2_SMEM>>>(ctxh, woh, attn_h, 4096, 2048, 2048);
    add_ln_k<float, half_t><<<4096, 256>>>(x, attn_h, ln1g, ln1b, nullptr, h1h);

    // FFN: fused gate|up GEMM (N=16384), silu, down-proj (fp16 out)
    gemm2<half_t><<<dim3(64, 32), 256, G2_SMEM>>>(h1h, guwh, gu_h, 4096, 16384, 2048);
    silu_mul_f<<<16384, 256>>>(gu_h, acth);
    gemm2<half_t><<<dim3(8, 32), 256, G2_SMEM>>>(acth, dwh, ffn_h, 4096, 2048, 8192);

    // residual (fp16 h1) + LN2 -> output
    add_ln_k<half_t, half_t><<<4096, 256>>>(h1h, ffn_h, ln2g, ln2b, out, nullptr);
}

// round 17
// speedup vs baseline: 1.3909x; 1.0036x over previous
#include <cuda_runtime.h>
#include <mma.h>
#include <cstdint>

using namespace nvcuda;
typedef __half half_t;

// Problem dims: B=8, S=512, D=2048, H=32, HD=64, I=8192, NT=4096 tokens.

// ---------------- scratch (device globals; no allocation allowed) --------
__device__ float  g_tmp[4096 * 8192];    // gate|up fused fp16 [4096][16384]
__device__ float  g_up [4096 * 8192];    // ffn_out fp16 (aliased)
__device__ float  g_rm [1023];           // rel_pos row means
// fp16 operands
__device__ half_t g_xh   [4096 * 2048];
__device__ half_t g_qkvh [4096 * 6144];
__device__ half_t g_ctxh [4096 * 2048];
__device__ half_t g_h1h  [4096 * 2048];
__device__ half_t g_acth [4096 * 8192];  // attn_out fp16, later silu act
__device__ half_t g_wqkvh[2048 * 6144];  // [K=2048][Nq|Nk|Nv]
__device__ half_t g_woh  [2048 * 2048];
__device__ half_t g_guwh [2048 * 16384]; // [K=2048][gate8192|up8192]
__device__ half_t g_dwh  [8192 * 2048];

// ---------------- small helpers ------------------------------------------
__device__ __forceinline__ uint32_t smem_u32(const void* p) {
    uint32_t a;
    asm("{ .reg .u64 t; cvta.to.shared.u64 t, %1; cvt.u32.u64 %0, t; }"
        : "=r"(a) : "l"(p));
    return a;
}
__device__ __forceinline__ void cpa16(uint32_t dst, const void* src) {
    asm volatile("cp.async.cg.shared.global [%0], [%1], 16;"
                 :: "r"(dst), "l"(src) : "memory");
}
__device__ __forceinline__ void cpa_commit() {
    asm volatile("cp.async.commit_group;" ::: "memory");
}
template <int N>
__device__ __forceinline__ void cpa_wait() {
    asm volatile("cp.async.wait_group %0;" :: "n"(N) : "memory");
}

__device__ __forceinline__ float bred(float v, int op_max) {
    __shared__ float red[8];
    #pragma unroll
    for (int o = 16; o; o >>= 1) {
        float w = __shfl_xor_sync(0xffffffffu, v, o);
        v = op_max ? fmaxf(v, w) : v + w;
    }
    __syncthreads();
    if ((threadIdx.x & 31) == 0) red[threadIdx.x >> 5] = v;
    __syncthreads();
    v = red[threadIdx.x & 7];
    #pragma unroll
    for (int o = 4; o; o >>= 1) {
        float w = __shfl_xor_sync(0xffffffffu, v, o);
        v = op_max ? fmaxf(v, w) : v + w;
    }
    return v;
}

// =================== fp16 GEMM: C[M,N] = A[M,K] @ B[K,N] ==================
// Block tile 128x256, BK=32, 256 threads = 8 warps (2x4), warptile 64x64.
// 4-stage cp.async, ONE __syncthreads per K-iteration. (Best-measured config.)
#define G2_LDA   40
#define G2_LDB   264
#define G2_ASTG  10240                    // 128*40*2
#define G2_BSTG  16896                    // 32*264*2
#define G2_STG   27136
#define G2_SMEM  (4 * G2_STG)             // 108544
#define G2_LDC   132

template <typename OutT>
__global__ void __launch_bounds__(256, 1) gemm2(
    const half_t* __restrict__ A, const half_t* __restrict__ B,
    OutT* __restrict__ C, int M, int N, int K)
{
    extern __shared__ __align__(128) char smem[];
    const uint32_t sb = smem_u32(smem);
    const int tid = threadIdx.x;
    const int warp = tid >> 5;
    const int bm = blockIdx.y * 128, bn = blockIdx.x * 256;
    const int wm = (warp >> 2) * 64, wn = (warp & 3) * 64;

    const int ar0 = tid >> 2,         ac0 = (tid & 3) << 3;
    const int ar1 = (tid + 256) >> 2, ac1 = ((tid + 256) & 3) << 3;
    const int brb = tid >> 5,         bc  = (tid & 31) << 3;

    const half_t* Abm = A + (size_t)bm * K;
    const half_t* Bbn = B + bn;

    auto load_stage = [&](int s, int kt) {
        const int k0 = kt * 32;
        uint32_t aB = sb + s * G2_STG;
        uint32_t bB = aB + G2_ASTG;
        cpa16(aB + (ar0 * G2_LDA + ac0) * 2, Abm + (size_t)ar0 * K + k0 + ac0);
        cpa16(aB + (ar1 * G2_LDA + ac1) * 2, Abm + (size_t)ar1 * K + k0 + ac1);
        #pragma unroll
        for (int i = 0; i < 4; i++) {
            int r = brb + 8 * i;
            cpa16(bB + (r * G2_LDB + bc) * 2, Bbn + (size_t)(k0 + r) * N + bc);
        }
    };

    wmma::fragment<wmma::accumulator, 16, 16, 16, float> acc[4][4];
    #pragma unroll
    for (int i = 0; i < 4; i++)
        #pragma unroll
        for (int j = 0; j < 4; j++)
            wmma::fill_fragment(acc[i][j], 0.0f);

    const int KT = K >> 5;
    #pragma unroll
    for (int s = 0; s < 3; s++) { load_stage(s, s); cpa_commit(); }

    for (int kt = 0; kt < KT; kt++) {
        cpa_wait<2>();
        __syncthreads();

        if (kt + 3 < KT) load_stage((kt + 3) & 3, kt + 3);
        cpa_commit();

        const int s = kt & 3;
        const half_t* As = (const half_t*)(smem + s * G2_STG);
        const half_t* Bs = (const half_t*)(smem + s * G2_STG + G2_ASTG);
        #pragma unroll
        for (int ks = 0; ks < 2; ks++) {
            wmma::fragment<wmma::matrix_a, 16, 16, 16, half_t, wmma::row_major> af[4];
            wmma::fragment<wmma::matrix_b, 16, 16, 16, half_t, wmma::row_major> bf[4];
            #pragma unroll
            for (int i = 0; i < 4; i++)
                wmma::load_matrix_sync(af[i], As + (wm + i * 16) * G2_LDA + ks * 16, G2_LDA);
            #pragma unroll
            for (int j = 0; j < 4; j++)
                wmma::load_matrix_sync(bf[j], Bs + (ks * 16) * G2_LDB + wn + j * 16, G2_LDB);
            #pragma unroll
            for (int i = 0; i < 4; i++)
                #pragma unroll
                for (int j = 0; j < 4; j++)
                    wmma::mma_sync(acc[i][j], af[i], bf[j], acc[i][j]);
        }
    }

    // 2-phase epilogue through fp32 smem staging
    float* Cs = (float*)smem;
    #pragma unroll
    for (int ph = 0; ph < 2; ph++) {
        __syncthreads();
        if (((warp & 3) >> 1) == ph) {
            int lwn = (warp & 3) & 1;
            #pragma unroll
            for (int i = 0; i < 4; i++)
                #pragma unroll
                for (int j = 0; j < 4; j++)
                    wmma::store_matrix_sync(Cs + (wm + i * 16) * G2_LDC + lwn * 64 + j * 16,
                                            acc[i][j], G2_LDC, wmma::mem_row_major);
        }
        __syncthreads();
        #pragma unroll
        for (int it = 0; it < 16; it++) {
            int idx = tid + 256 * it;
            int r = idx >> 5, c = (idx & 31) << 2;
            float4 v = *(float4*)(Cs + r * G2_LDC + c);
            if constexpr (sizeof(OutT) == 4) {
                *(float4*)((float*)C + (size_t)(bm + r) * N + bn + ph * 128 + c) = v;
            } else {
                half2 h0 = __floats2half2_rn(v.x, v.y);
                half2 h1 = __floats2half2_rn(v.z, v.w);
                *(uint2*)((half_t*)C + (size_t)(bm + r) * N + bn + ph * 128 + c) =
                    make_uint2(*(uint32_t*)&h0, *(uint32_t*)&h1);
            }
        }
    }
}

// =================== fused flash attention (in-fragment softmax) ==========
#define FL_RM   0
#define FL_QS   4096
#define FL_KS   (FL_QS + 18432)
#define FL_VS   (FL_KS + 18432)
#define FL_PS   (FL_VS + 18432)           // fp16 [128][136] = 34816
#define FL_PMAX (FL_PS + 34816)           // [4][128] f32
#define FL_PSUM (FL_PMAX + 2048)          // [4][128] f32
#define FL_M    (FL_PSUM + 2048)
#define FL_L    (FL_M + 512)
#define FL_CORR (FL_L + 512)
#define FL_SMEM (FL_CORR + 512)           // 99840

__global__ void __launch_bounds__(256, 1) flash_k(
    const half_t* __restrict__ qkv, const float* __restrict__ rmg,
    half_t* __restrict__ ctx)
{
    extern __shared__ __align__(128) char smem[];
    float*  rms  = (float*)(smem + FL_RM);
    half_t* Qs   = (half_t*)(smem + FL_QS);
    half_t* Ks   = (half_t*)(smem + FL_KS);
    half_t* Vs   = (half_t*)(smem + FL_VS);
    half_t* Ps   = (half_t*)(smem + FL_PS);
    float*  pmax = (float*)(smem + FL_PMAX);
    float*  psum = (float*)(smem + FL_PSUM);
    float*  mS   = (float*)(smem + FL_M);
    float*  lS   = (float*)(smem + FL_L);
    float*  cS   = (float*)(smem + FL_CORR);

    const int tid = threadIdx.x, warp = tid >> 5, lane = tid & 31;
    const int bz = blockIdx.y, b = bz >> 5, h = bz & 31;
    const int q0 = blockIdx.x * 128;
    const int wm = (warp >> 2) * 64, wnc = (warp & 3) * 32;
    const int lr = lane >> 2, lc = (lane & 3) * 2;

    for (int i = tid; i < 1023; i += 256) rms[i] = rmg[i];

    const half_t* qp = qkv + ((size_t)(b * 512 + q0)) * 6144 + h * 64;
    #pragma unroll
    for (int i = 0; i < 4; i++) {
        int idx = tid + 256 * i;
        int r = idx >> 3, c = (idx & 7) << 3;
        *(uint4*)(Qs + r * 72 + c) = *(const uint4*)(qp + (size_t)r * 6144 + c);
    }
    if (tid < 128) { mS[tid] = -1e30f; lS[tid] = 0.0f; }

    wmma::fragment<wmma::accumulator, 16, 16, 16, float> oa[4];
    #pragma unroll
    for (int j = 0; j < 4; j++) wmma::fill_fragment(oa[j], 0.0f);

    __syncthreads();

    for (int kt = 0; kt < 4; kt++) {
        const int k0 = kt * 128;
        const half_t* kp = qkv + ((size_t)(b * 512 + k0)) * 6144 + 2048 + h * 64;
        const half_t* vp = qkv + ((size_t)(b * 512 + k0)) * 6144 + 4096 + h * 64;
        #pragma unroll
        for (int i = 0; i < 4; i++) {
            int idx = tid + 256 * i;
            int r = idx >> 3, c = (idx & 7) << 3;
            *(uint4*)(Ks + r * 72 + c) = *(const uint4*)(kp + (size_t)r * 6144 + c);
            *(uint4*)(Vs + r * 72 + c) = *(const uint4*)(vp + (size_t)r * 6144 + c);
        }
        __syncthreads();

        // ---- S = Q @ K^T, kept in fragments ----
        wmma::fragment<wmma::accumulator, 16, 16, 16, float> sa[4][2];
        #pragma unroll
        for (int i = 0; i < 4; i++)
            #pragma unroll
            for (int j = 0; j < 2; j++)
                wmma::fill_fragment(sa[i][j], 0.0f);
        #pragma unroll
        for (int ks = 0; ks < 4; ks++) {
            wmma::fragment<wmma::matrix_a, 16, 16, 16, half_t, wmma::row_major> af[4];
            wmma::fragment<wmma::matrix_b, 16, 16, 16, half_t, wmma::col_major> bf[2];
            #pragma unroll
            for (int i = 0; i < 4; i++)
                wmma::load_matrix_sync(af[i], Qs + (wm + i * 16) * 72 + ks * 16, 72);
            #pragma unroll
            for (int j = 0; j < 2; j++)
                wmma::load_matrix_sync(bf[j], Ks + (wnc + j * 16) * 72 + ks * 16, 72);
            #pragma unroll
            for (int i = 0; i < 4; i++)
                #pragma unroll
                for (int j = 0; j < 2; j++)
                    wmma::mma_sync(sa[i][j], af[i], bf[j], sa[i][j]);
        }

        // ---- in-place scale+bias, per-thread row maxes ----
        float pmx[8];
        #pragma unroll
        for (int k = 0; k < 8; k++) pmx[k] = -1e30f;
        #pragma unroll
        for (int i = 0; i < 4; i++)
            #pragma unroll
            for (int j = 0; j < 2; j++)
                #pragma unroll
                for (int p = 0; p < 4; p++) {
                    int r = wm + i * 16 + lr + ((p & 1) << 3);
                    int c = wnc + j * 16 + lc + ((p >> 1) << 3);
                    int o = k0 + c - q0 - r + 511;
                    float v0 = sa[i][j].x[2 * p] * 0.125f + rms[o];
                    float v1 = sa[i][j].x[2 * p + 1] * 0.125f + rms[o + 1];
                    sa[i][j].x[2 * p] = v0;
                    sa[i][j].x[2 * p + 1] = v1;
                    int rid = i * 2 + (p & 1);
                    pmx[rid] = fmaxf(pmx[rid], fmaxf(v0, v1));
                }
        #pragma unroll
        for (int k = 0; k < 8; k++) {
            pmx[k] = fmaxf(pmx[k], __shfl_xor_sync(0xffffffffu, pmx[k], 1));
            pmx[k] = fmaxf(pmx[k], __shfl_xor_sync(0xffffffffu, pmx[k], 2));
        }
        if ((lane & 3) == 0) {
            #pragma unroll
            for (int i = 0; i < 4; i++) {
                pmax[(warp & 3) * 128 + wm + i * 16 + lr]     = pmx[i * 2];
                pmax[(warp & 3) * 128 + wm + i * 16 + lr + 8] = pmx[i * 2 + 1];
            }
        }
        __syncthreads();

        // ---- row stats (designated lanes) ----
        if ((warp & 3) == 0 && (lane & 3) == 0) {
            #pragma unroll
            for (int i = 0; i < 4; i++)
                #pragma unroll
                for (int h2 = 0; h2 < 2; h2++) {
                    int r = wm + i * 16 + lr + h2 * 8;
                    float mo = mS[r];
                    float mn = fmaxf(fmaxf(fmaxf(pmax[r], pmax[128 + r]),
                                           fmaxf(pmax[256 + r], pmax[384 + r])), mo);
                    cS[r] = __expf(mo - mn);
                    mS[r] = mn;
                }
        }
        __syncthreads();

        // ---- exp in-fragment -> Ps, partial row sums ----
        float mn8[8];
        #pragma unroll
        for (int i = 0; i < 4; i++) {
            mn8[i * 2]     = mS[wm + i * 16 + lr];
            mn8[i * 2 + 1] = mS[wm + i * 16 + lr + 8];
        }
        float psm[8];
        #pragma unroll
        for (int k = 0; k < 8; k++) psm[k] = 0.0f;
        #pragma unroll
        for (int i = 0; i < 4; i++)
            #pragma unroll
            for (int j = 0; j < 2; j++)
                #pragma unroll
                for (int p = 0; p < 4; p++) {
                    int rid = i * 2 + (p & 1);
                    int r = wm + i * 16 + lr + ((p & 1) << 3);
                    int c = wnc + j * 16 + lc + ((p >> 1) << 3);
                    float e0 = __expf(sa[i][j].x[2 * p]     - mn8[rid]);
                    float e1 = __expf(sa[i][j].x[2 * p + 1] - mn8[rid]);
                    psm[rid] += e0 + e1;
                    *(half2*)(Ps + r * 136 + c) = __floats2half2_rn(e0, e1);
                }
        #pragma unroll
        for (int k = 0; k < 8; k++) {
            psm[k] += __shfl_xor_sync(0xffffffffu, psm[k], 1);
            psm[k] += __shfl_xor_sync(0xffffffffu, psm[k], 2);
        }
        if ((lane & 3) == 0) {
            #pragma unroll
            for (int i = 0; i < 4; i++) {
                psum[(warp & 3) * 128 + wm + i * 16 + lr]     = psm[i * 2];
                psum[(warp & 3) * 128 + wm + i * 16 + lr + 8] = psm[i * 2 + 1];
            }
        }
        __syncthreads();

        // ---- lS update (designated) overlaps O rescale + PV (all) ----
        if ((warp & 3) == 0 && (lane & 3) == 0) {
            #pragma unroll
            for (int i = 0; i < 4; i++)
                #pragma unroll
                for (int h2 = 0; h2 < 2; h2++) {
                    int r = wm + i * 16 + lr + h2 * 8;
                    lS[r] = lS[r] * cS[r] +
                            (psum[r] + psum[128 + r]) + (psum[256 + r] + psum[384 + r]);
                }
        }
        {
            float co0 = cS[warp * 16 + lr];
            float co1 = cS[warp * 16 + lr + 8];
            #pragma unroll
            for (int j = 0; j < 4; j++) {
                oa[j].x[0] *= co0; oa[j].x[1] *= co0;
                oa[j].x[4] *= co0; oa[j].x[5] *= co0;
                oa[j].x[2] *= co1; oa[j].x[3] *= co1;
                oa[j].x[6] *= co1; oa[j].x[7] *= co1;
            }
            #pragma unroll
            for (int ks = 0; ks < 8; ks++) {
                wmma::fragment<wmma::matrix_a, 16, 16, 16, half_t, wmma::row_major> af;
                wmma::fragment<wmma::matrix_b, 16, 16, 16, half_t, wmma::row_major> bf[4];
                wmma::load_matrix_sync(af, Ps + (warp * 16) * 136 + ks * 16, 136);
                #pragma unroll
                for (int j = 0; j < 4; j++)
                    wmma::load_matrix_sync(bf[j], Vs + (ks * 16) * 72 + j * 16, 72);
                #pragma unroll
                for (int j = 0; j < 4; j++)
                    wmma::mma_sync(oa[j], af, bf[j], oa[j]);
            }
        }
        __syncthreads();
    }

    // ---- final: O /= l, stage into dead Ks/Vs region, write fp16 ----
    float* Os = (float*)(smem + FL_KS);
    {
        float inv0 = 1.0f / lS[warp * 16 + lr];
        float inv1 = 1.0f / lS[warp * 16 + lr + 8];
        #pragma unroll
        for (int j = 0; j < 4; j++) {
            oa[j].x[0] *= inv0; oa[j].x[1] *= inv0;
            oa[j].x[4] *= inv0; oa[j].x[5] *= inv0;
            oa[j].x[2] *= inv1; oa[j].x[3] *= inv1;
            oa[j].x[6] *= inv1; oa[j].x[7] *= inv1;
        }
        #pragma unroll
        for (int j = 0; j < 4; j++)
            wmma::store_matrix_sync(Os + (warp * 16) * 72 + j * 16,
                                    oa[j], 72, wmma::mem_row_major);
    }
    __syncthreads();

    half_t* cp = ctx + ((size_t)(b * 512 + q0)) * 2048 + h * 64;
    #pragma unroll
    for (int i = 0; i < 8; i++) {
        int idx = tid + 256 * i;
        int r = idx >> 4, c = (idx & 15) << 2;
        float4 ov = *(float4*)(Os + r * 72 + c);
        half2 h0 = __floats2half2_rn(ov.x, ov.y);
        half2 h1 = __floats2half2_rn(ov.z, ov.w);
        *(uint2*)(cp + (size_t)r * 2048 + c) =
            make_uint2(*(uint32_t*)&h0, *(uint32_t*)&h1);
    }
}

// ---------------- residual add + layernorm (row = 2048) ------------------
template <typename XT, typename YT>
__global__ void __launch_bounds__(256) add_ln_k(
    const XT* __restrict__ xr, const YT* __restrict__ yr,
    const float* __restrict__ g, const float* __restrict__ bt,
    float* __restrict__ out, half_t* __restrict__ hout)
{
    size_t row = blockIdx.x;
    int t = threadIdx.x;
    float v[8];
    #pragma unroll
    for (int i = 0; i < 2; i++) {
        int c4 = t + 256 * i;
        float xv[4], yv[4];
        if constexpr (sizeof(XT) == 4) {
            float4 a = *(const float4*)((const float*)xr + row * 2048 + c4 * 4);
            xv[0] = a.x; xv[1] = a.y; xv[2] = a.z; xv[3] = a.w;
        } else {
            uint2 p = *(const uint2*)((const half_t*)xr + row * 2048 + c4 * 4);
            float2 f0 = __half22float2(*(half2*)&p.x);
            float2 f1 = __half22float2(*(half2*)&p.y);
            xv[0] = f0.x; xv[1] = f0.y; xv[2] = f1.x; xv[3] = f1.y;
        }
        if constexpr (sizeof(YT) == 4) {
            float4 c = *(const float4*)((const float*)yr + row * 2048 + c4 * 4);
            yv[0] = c.x; yv[1] = c.y; yv[2] = c.z; yv[3] = c.w;
        } else {
            uint2 p = *(const uint2*)((const half_t*)yr + row * 2048 + c4 * 4);
            float2 f0 = __half22float2(*(half2*)&p.x);
            float2 f1 = __half22float2(*(half2*)&p.y);
            yv[0] = f0.x; yv[1] = f0.y; yv[2] = f1.x; yv[3] = f1.y;
        }
        v[4 * i + 0] = xv[0] + yv[0]; v[4 * i + 1] = xv[1] + yv[1];
        v[4 * i + 2] = xv[2] + yv[2]; v[4 * i + 3] = xv[3] + yv[3];
    }
    float s = 0.0f;
    #pragma unroll
    for (int i = 0; i < 8; i++) s += v[i];
    float mu = bred(s, 0) * (1.0f / 2048.0f);
    float qs = 0.0f;
    #pragma unroll
    for (int i = 0; i < 8; i++) { float d = v[i] - mu; qs += d * d; }
    float rstd = rsqrtf(bred(qs, 0) * (1.0f / 2048.0f) + 1e-6f);
    #pragma unroll
    for (int i = 0; i < 2; i++) {
        int c4 = t + 256 * i;
        float4 gv = ((const float4*)g)[c4];
        float4 bv = ((const float4*)bt)[c4];
        float4 o;
        o.x = (v[4 * i + 0] - mu) * rstd * gv.x + bv.x;
        o.y = (v[4 * i + 1] - mu) * rstd * gv.y + bv.y;
        o.z = (v[4 * i + 2] - mu) * rstd * gv.z + bv.z;
        o.w = (v[4 * i + 3] - mu) * rstd * gv.w + bv.w;
        if (out) *(float4*)(out + row * 2048 + c4 * 4) = o;
        if (hout) {
            half2 h0 = __floats2half2_rn(o.x, o.y);
            half2 h1 = __floats2half2_rn(o.z, o.w);
            *(uint2*)(hout + row * 2048 + c4 * 4) =
                make_uint2(*(uint32_t*)&h0, *(uint32_t*)&h1);
        }
    }
}

// ---------------- silu(gate)*up from fused [4096][16384] ------------------
// 16 halves/thread: 2x uint4 from gate + 2x uint4 from up in flight.
__global__ void __launch_bounds__(256) silu_mul_f(
    const half_t* __restrict__ gu, half_t* __restrict__ act)
{
    size_t idx = ((size_t)blockIdx.x * 256 + threadIdx.x) * 16;
    size_t row = idx >> 13, col = idx & 8191;
    const half_t* gp = gu + row * 16384 + col;
    uint4 g0 = *(const uint4*)(gp);
    uint4 g1 = *(const uint4*)(gp + 8);
    uint4 u0 = *(const uint4*)(gp + 8192);
    uint4 u1 = *(const uint4*)(gp + 8200);
    uint4 r0, r1;
    const half2* gg0 = (const half2*)&g0;
    const half2* gg1 = (const half2*)&g1;
    const half2* uu0 = (const half2*)&u0;
    const half2* uu1 = (const half2*)&u1;
    half2* rr0 = (half2*)&r0;
    half2* rr1 = (half2*)&r1;
    #pragma unroll
    for (int j = 0; j < 4; j++) {
        float2 gf = __half22float2(gg0[j]);
        float2 uf = __half22float2(uu0[j]);
        rr0[j] = __floats2half2_rn(gf.x / (1.0f + __expf(-gf.x)) * uf.x,
                                   gf.y / (1.0f + __expf(-gf.y)) * uf.y);
        float2 gf1 = __half22float2(gg1[j]);
        float2 uf1 = __half22float2(uu1[j]);
        rr1[j] = __floats2half2_rn(gf1.x / (1.0f + __expf(-gf1.x)) * uf1.x,
                                   gf1.y / (1.0f + __expf(-gf1.y)) * uf1.y);
    }
    *(uint4*)(act + idx) = r0;
    *(uint4*)(act + idx + 8) = r1;
}

// ---------------- conversions ---------------------------------------------
__device__ __forceinline__ void conv16(const float* in, half_t* out) {
    float4 a0 = *(const float4*)(in + 0);
    float4 a1 = *(const float4*)(in + 4);
    float4 a2 = *(const float4*)(in + 8);
    float4 a3 = *(const float4*)(in + 12);
    half2 h0 = __floats2half2_rn(a0.x, a0.y), h1 = __floats2half2_rn(a0.z, a0.w);
    half2 h2 = __floats2half2_rn(a1.x, a1.y), h3 = __floats2half2_rn(a1.z, a1.w);
    half2 h4 = __floats2half2_rn(a2.x, a2.y), h5 = __floats2half2_rn(a2.z, a2.w);
    half2 h6 = __floats2half2_rn(a3.x, a3.y), h7 = __floats2half2_rn(a3.z, a3.w);
    *(uint4*)(out + 0) = make_uint4(*(uint32_t*)&h0, *(uint32_t*)&h1,
                                    *(uint32_t*)&h2, *(uint32_t*)&h3);
    *(uint4*)(out + 8) = make_uint4(*(uint32_t*)&h4, *(uint32_t*)&h5,
                                    *(uint32_t*)&h6, *(uint32_t*)&h7);
}

// stream 0: x + wq/wk/wv + rowmean (everything QKV GEMM needs)
__global__ void __launch_bounds__(256) conv_qkv(
    const float* __restrict__ x,  half_t* __restrict__ xo,
    const float* __restrict__ wq, const float* __restrict__ wk,
    const float* __restrict__ wv, half_t* __restrict__ wqkv,
    const float* __restrict__ rel, float* __restrict__ rm)
{
    int blk = blockIdx.x;
    const int t = threadIdx.x;
    if (blk >= 5120) {
        int r = (blk - 5120) * 256 + t;
        if (r < 1023) {
            float s = 0.0f;
            #pragma unroll
            for (int d = 0; d < 64; d += 4) {
                float4 vv = *(const float4*)(rel + (size_t)r * 64 + d);
                s += (vv.x + vv.y) + (vv.z + vv.w);
            }
            rm[r] = s * (1.0f / 64.0f);
        }
        return;
    }
    if (blk < 2048) {
        size_t i = ((size_t)blk * 256 + t) * 16;
        conv16(x + i, xo + i);
        return;
    }
    int sec = (blk - 2048) >> 10;
    const float* in = sec == 0 ? wq : (sec == 1 ? wk : wv);
    size_t i = ((size_t)((blk - 2048) & 1023) * 256 + t) * 16;
    int r = (int)(i >> 11), c = (int)(i & 2047);
    conv16(in + i, wqkv + (size_t)r * 6144 + sec * 2048 + c);
}

// stream 2 (overlapped): wo + gw|uw fused contiguous + dw
__global__ void __launch_bounds__(256) conv_rest(
    const float* __restrict__ wo, half_t* __restrict__ woo,
    const float* __restrict__ gw, const float* __restrict__ uw,
    half_t* __restrict__ guw,
    const float* __restrict__ dw, half_t* __restrict__ dwo)
{
    int blk = blockIdx.x;
    const int t = threadIdx.x;
    if (blk < 1024) {
        size_t i = ((size_t)blk * 256 + t) * 16;
        conv16(wo + i, woo + i);
        return;
    }
    if (blk < 5120) {
        size_t i = ((size_t)(blk - 1024) * 256 + t) * 16;
        size_t r = i >> 13, c = i & 8191;
        conv16(gw + i, guw + r * 16384 + c);
        return;
    }
    if (blk < 9216) {
        size_t i = ((size_t)(blk - 5120) * 256 + t) * 16;
        size_t r = i >> 13, c = i & 8191;
        conv16(uw + i, guw + r * 16384 + 8192 + c);
        return;
    }
    size_t i = ((size_t)(blk - 9216) * 256 + t) * 16;
    conv16(dw + i, dwo + i);
}

// =================== host side ============================================
extern "C" void kernel_launch(void* const* d_in, const int* in_sizes, int n_in,
                              void* d_out, int out_size)
{
    (void)in_sizes; (void)n_in; (void)out_size;
    const float* x    = (const float*)d_in[0];
    const float* wq   = (const float*)d_in[1];
    const float* wk   = (const float*)d_in[2];
    const float* wv   = (const float*)d_in[3];
    const float* wo   = (const float*)d_in[4];
    const float* rel  = (const float*)d_in[5];
    const float* ln1g = (const float*)d_in[6];
    const float* ln1b = (const float*)d_in[7];
    const float* gw   = (const float*)d_in[8];
    const float* uw   = (const float*)d_in[9];
    const float* dw   = (const float*)d_in[10];
    const float* ln2g = (const float*)d_in[11];
    const float* ln2b = (const float*)d_in[12];
    float* out = (float*)d_out;

    float *tmp, *up, *rm;
    half_t *xh, *qkvh, *ctxh, *h1h, *acth;
    half_t *wqkvh, *woh, *guwh, *dwh;
    cudaGetSymbolAddress((void**)&tmp,   g_tmp);
    cudaGetSymbolAddress((void**)&up,    g_up);
    cudaGetSymbolAddress((void**)&rm,    g_rm);
    cudaGetSymbolAddress((void**)&xh,    g_xh);
    cudaGetSymbolAddress((void**)&qkvh,  g_qkvh);
    cudaGetSymbolAddress((void**)&ctxh,  g_ctxh);
    cudaGetSymbolAddress((void**)&h1h,   g_h1h);
    cudaGetSymbolAddress((void**)&acth,  g_acth);
    cudaGetSymbolAddress((void**)&wqkvh, g_wqkvh);
    cudaGetSymbolAddress((void**)&woh,   g_woh);
    cudaGetSymbolAddress((void**)&guwh,  g_guwh);
    cudaGetSymbolAddress((void**)&dwh,   g_dwh);

    half_t* gu_h   = (half_t*)tmp;   // fused gate|up output [4096][16384]
    half_t* attn_h = acth;           // attn_out (dead before silu writes acth)
    half_t* ffn_h  = (half_t*)up;    // down-proj fp16 output

    static cudaStream_t s2 = nullptr;
    static cudaEvent_t evFork = nullptr, evJoin = nullptr;
    if (!s2) {
        cudaStreamCreateWithFlags(&s2, cudaStreamNonBlocking);
        cudaEventCreateWithFlags(&evFork, cudaEventDisableTiming);
        cudaEventCreateWithFlags(&evJoin, cudaEventDisableTiming);
    }

    cudaFuncSetAttribute((const void*)gemm2<half_t>,
        cudaFuncAttributeMaxDynamicSharedMemorySize, G2_SMEM);
    cudaFuncSetAttribute((const void*)gemm2<float>,
        cudaFuncAttributeMaxDynamicSharedMemorySize, G2_SMEM);
    cudaFuncSetAttribute((const void*)flash_k,
        cudaFuncAttributeMaxDynamicSharedMemorySize, FL_SMEM);

    // fork: FFN/WO weight conversion overlaps QKV GEMM + flash on stream s2
    cudaEventRecord(evFork, 0);
    cudaStreamWaitEvent(s2, evFork, 0);
    conv_rest<<<13312, 256, 0, s2>>>(wo, woh, gw, uw, guwh, dw, dwh);

    // main stream: QKV-critical conversions, then QKV GEMM + flash
    conv_qkv<<<5124, 256>>>(x, xh, wq, wk, wv, wqkvh, rel, rm);
    gemm2<half_t><<<dim3(24, 32), 256, G2_SMEM>>>(xh, wqkvh, qkvh, 4096, 6144, 2048);
    flash_k<<<dim3(4, 256), 256, FL_SMEM>>>(qkvh, rm, ctxh);

    // join: WO GEMM needs woh from s2
    cudaEventRecord(evJoin, s2);
    cudaStreamWaitEvent(0, evJoin, 0);

    // output projection + residual + LN1 (fp16 h1 only)
    gemm2<half_t><<<dim3(8, 32), 256, G2_SMEM>>>(ctxh, woh, attn_h, 4096, 2048, 2048);
    add_ln_k<float, half_t><<<4096, 256>>>(x, attn_h, ln1g, ln1b, nullptr, h1h);

    // FFN: fused gate|up GEMM (N=16384), silu (16 halves/thread), down-proj
    gemm2<half_t><<<dim3(64, 32), 256, G2_SMEM>>>(h1h, guwh, gu_h, 4096, 16384, 2048);
    silu_mul_f<<<8192, 256>>>(gu_h, acth);
    gemm2<half_t><<<dim3(8, 32), 256, G2_SMEM>>>(acth, dwh, ffn_h, 4096, 2048, 8192);

    // residual (fp16 h1) + LN2 -> output
    add_ln_k<half_t, half_t><<<4096, 256>>>(h1h, ffn_h, ln2g, ln2b, out, nullptr);
}